// round 1
// baseline (speedup 1.0000x reference)
#include <cuda_runtime.h>
#include <cstdint>

#define BATCH 8
#define NPRI 57744
#define NCLS 81
#define NOBJ 20
#define ROWS (BATCH * NPRI)   // 461952

#define NEGINF __int_as_float(0xff800000)

// ---------------- device scratch (no allocation allowed) ----------------
__device__ unsigned long long g_bestPrior[BATCH * NOBJ]; // packed (iou_bits<<32)|~p
__device__ float    g_bto[ROWS];      // best truth overlap per prior
__device__ int      g_bti[ROWS];      // best truth idx per prior
__device__ unsigned g_keys[ROWS];     // ordered score key, 0 = not a neg candidate
__device__ float    g_ceneg[ROWS];    // neg CE per candidate
__device__ unsigned g_hist1[65536];
__device__ unsigned g_hist2[65536];
__device__ float    g_sl1, g_cepos, g_cenegsum;
__device__ unsigned g_numpos, g_bhi, g_r, g_keyT, g_take, g_takeAll, g_negGT, g_eqcnt;
__device__ unsigned g_eq[4096];

// ---------------- helpers ----------------
__device__ __forceinline__ float wmaxf(float v) {
    #pragma unroll
    for (int o = 16; o; o >>= 1) v = fmaxf(v, __shfl_xor_sync(0xffffffffu, v, o));
    return v;
}
__device__ __forceinline__ float wsumf(float v) {
    #pragma unroll
    for (int o = 16; o; o >>= 1) v += __shfl_xor_sync(0xffffffffu, v, o);
    return v;
}
__device__ __forceinline__ unsigned f2key(float f) {
    unsigned u = __float_as_uint(f);
    return (u & 0x80000000u) ? ~u : (u | 0x80000000u);
}

// ---------------- kernels ----------------
__global__ void k_init() {
    int gid = blockIdx.x * blockDim.x + threadIdx.x;
    if (gid < 65536) g_hist1[gid] = 0u;
    else if (gid < 131072) g_hist2[gid - 65536] = 0u;
    if (gid < BATCH * NOBJ) g_bestPrior[gid] = 0ull;
    if (gid == 0) {
        g_sl1 = 0.f; g_cepos = 0.f; g_cenegsum = 0.f;
        g_numpos = 0u; g_bhi = 0u; g_r = 0u; g_keyT = 0u; g_take = 0u;
        g_takeAll = 0u; g_negGT = 0u; g_eqcnt = 0u;
    }
}

__global__ void k_match(const float* __restrict__ priors,
                        const float* __restrict__ gt_boxes) {
    int b = blockIdx.y;
    int p = blockIdx.x * blockDim.x + threadIdx.x;
    int lane = threadIdx.x & 31;
    __shared__ float4 sgt[NOBJ];
    __shared__ float  sga[NOBJ];
    __shared__ unsigned long long sbest[NOBJ];
    if (threadIdx.x < NOBJ) {
        float4 g = ((const float4*)gt_boxes)[b * NOBJ + threadIdx.x];
        sgt[threadIdx.x] = g;
        sga[threadIdx.x] = (g.z - g.x) * (g.w - g.y);
        sbest[threadIdx.x] = 0ull;
    }
    __syncthreads();

    bool valid = (p < NPRI);
    float px1 = 0, py1 = 0, px2 = 0, py2 = 0, pa = 1.f;
    if (valid) {
        float4 pr = ((const float4*)priors)[p];
        px1 = pr.x - pr.z * 0.5f; py1 = pr.y - pr.w * 0.5f;
        px2 = pr.x + pr.z * 0.5f; py2 = pr.y + pr.w * 0.5f;
        pa = pr.z * pr.w;
    }
    float bestOv = -1.f; int bestN = 0;
    unsigned long long pk[NOBJ];
    #pragma unroll
    for (int n = 0; n < NOBJ; n++) {
        float iou = 0.f;
        if (valid) {
            float4 g = sgt[n];
            float ix = fmaxf(fminf(px2, g.z) - fmaxf(px1, g.x), 0.f);
            float iy = fmaxf(fminf(py2, g.w) - fmaxf(py1, g.y), 0.f);
            float inter = ix * iy;
            iou = inter / (pa + sga[n] - inter);
            if (iou > bestOv) { bestOv = iou; bestN = n; }
        }
        pk[n] = valid ? ((((unsigned long long)__float_as_uint(iou)) << 32) |
                         (unsigned long long)(~(unsigned)p)) : 0ull;
    }
    // warp reduce max of packed keys per gt
    #pragma unroll
    for (int n = 0; n < NOBJ; n++) {
        unsigned long long v = pk[n];
        #pragma unroll
        for (int o = 16; o; o >>= 1) {
            unsigned long long w = __shfl_xor_sync(0xffffffffu, v, o);
            if (w > v) v = w;
        }
        pk[n] = v;
    }
    if (lane == 0) {
        #pragma unroll
        for (int n = 0; n < NOBJ; n++) atomicMax(&sbest[n], pk[n]);
    }
    __syncthreads();
    if (threadIdx.x < NOBJ)
        atomicMax(&g_bestPrior[b * NOBJ + threadIdx.x], sbest[threadIdx.x]);
    if (valid) {
        g_bto[b * NPRI + p] = bestOv;
        g_bti[b * NPRI + p] = bestN;
    }
}

__global__ void k_force() {
    int b = threadIdx.x;
    if (b >= BATCH) return;
    for (int n = 0; n < NOBJ; n++) {   // sequential: last n wins on collisions
        unsigned long long v = g_bestPrior[b * NOBJ + n];
        unsigned p = ~(unsigned)(v & 0xFFFFFFFFull);
        g_bto[b * NPRI + p] = 2.0f;
        g_bti[b * NPRI + p] = n;
    }
}

__global__ void k_bigpass(const float* __restrict__ loc_data,
                          const float* __restrict__ conf,
                          const float* __restrict__ priors,
                          const float* __restrict__ gt_boxes,
                          const int*   __restrict__ gt_labels) {
    int warp = threadIdx.x >> 5;
    int lane = threadIdx.x & 31;
    int row = blockIdx.x * 8 + warp;   // grid sized so row < ROWS always

    __shared__ float s_sl1, s_cep;
    __shared__ unsigned s_np;
    if (threadIdx.x == 0) { s_sl1 = 0.f; s_cep = 0.f; s_np = 0u; }
    __syncthreads();

    const float* cr = conf + (size_t)row * NCLS;
    float v0 = cr[lane];
    float v1 = cr[lane + 32];
    float v2 = (lane < 17) ? cr[lane + 64] : NEGINF;

    float mAll = wmaxf(fmaxf(fmaxf(v0, v1), v2));
    float fg   = fmaxf((lane == 0 ? NEGINF : v0), fmaxf(v1, v2));
    float mFg  = wmaxf(fg);
    float e = __expf(v0 - mAll) + __expf(v1 - mAll) +
              ((lane < 17) ? __expf(v2 - mAll) : 0.f);
    float lse = mAll + __logf(wsumf(e));
    float conf0 = __shfl_sync(0xffffffffu, v0, 0);

    float ov; int n;
    if (lane == 0) { ov = g_bto[row]; n = g_bti[row]; }
    ov = __shfl_sync(0xffffffffu, ov, 0);
    n  = __shfl_sync(0xffffffffu, n, 0);

    int b = row / NPRI;
    int ct;
    if (ov < 0.4f) ct = 0;
    else if (ov < 0.5f) ct = -1;
    else {
        int label;
        if (lane == 0) label = gt_labels[b * NOBJ + n];
        ct = __shfl_sync(0xffffffffu, label, 0);
    }

    if (ct > 0) {
        float x = NEGINF;
        if (lane == ct) x = v0;
        if (lane + 32 == ct) x = v1;
        if (lane < 17 && lane + 64 == ct) x = v2;
        float cl = wmaxf(x);   // conf[row][ct]
        if (lane == 0) {
            int p = row - b * NPRI;
            float4 pr = ((const float4*)priors)[p];
            float4 g  = ((const float4*)gt_boxes)[b * NOBJ + n];
            float lt0 = ((g.x + g.z) * 0.5f - pr.x) / (0.1f * pr.z);
            float lt1 = ((g.y + g.w) * 0.5f - pr.y) / (0.1f * pr.w);
            float lt2 = logf((g.z - g.x) / pr.z) / 0.2f;
            float lt3 = logf((g.w - g.y) / pr.w) / 0.2f;
            const float* ld = loc_data + (size_t)row * 4;
            float lt[4] = {lt0, lt1, lt2, lt3};
            float s = 0.f;
            #pragma unroll
            for (int i = 0; i < 4; i++) {
                float d = ld[i] - lt[i];
                float a = fabsf(d);
                s += (a < 1.f) ? 0.5f * d * d : a - 0.5f;
            }
            atomicAdd(&s_sl1, s);
            atomicAdd(&s_cep, lse - cl);
            atomicAdd(&s_np, 1u);
            g_keys[row] = 0u;
        }
    } else if (lane == 0) {
        if (ct == 0) {
            unsigned key = f2key(mFg);
            if (key == 0u) key = 1u;
            g_keys[row] = key;
            g_ceneg[row] = lse - conf0;
            atomicAdd(&g_hist1[key >> 16], 1u);
        } else {
            g_keys[row] = 0u;
        }
    }
    __syncthreads();
    if (threadIdx.x == 0 && s_np) {
        atomicAdd(&g_numpos, s_np);
        atomicAdd(&g_sl1, s_sl1);
        atomicAdd(&g_cepos, s_cep);
    }
}

__global__ void k_select1() {
    __shared__ unsigned part[1024];
    __shared__ unsigned sTotal;
    int t = threadIdx.x;
    unsigned s = 0;
    #pragma unroll 8
    for (int j = 0; j < 64; j++) s += g_hist1[65535 - (t * 64 + j)];
    part[t] = s; __syncthreads();
    for (int off = 1; off < 1024; off <<= 1) {
        unsigned add = (t >= off) ? part[t - off] : 0u;
        __syncthreads();
        part[t] += add;
        __syncthreads();
    }
    unsigned incl = part[t], excl = incl - s;
    if (t == 1023) sTotal = incl;
    __syncthreads();
    unsigned total = sTotal;
    unsigned K = 3u * g_numpos;
    if (total <= K) {
        if (t == 0) { g_takeAll = 1u; g_keyT = 0u; g_take = 0u; }
        return;
    }
    if (excl < K && K <= incl) {
        unsigned cum = excl;
        for (int j = 0; j < 64; j++) {
            int bin = 65535 - (t * 64 + j);
            unsigned h = g_hist1[bin];
            if (K <= cum + h) { g_bhi = (unsigned)bin; g_r = K - cum; break; }
            cum += h;
        }
    }
}

__global__ void k_hist2() {
    int i = blockIdx.x * blockDim.x + threadIdx.x;
    if (i >= ROWS) return;
    if (g_takeAll) return;
    unsigned key = g_keys[i];
    if (key && (key >> 16) == g_bhi) atomicAdd(&g_hist2[key & 0xFFFFu], 1u);
}

__global__ void k_select2() {
    if (g_takeAll) return;
    __shared__ unsigned part[1024];
    int t = threadIdx.x;
    unsigned s = 0;
    #pragma unroll 8
    for (int j = 0; j < 64; j++) s += g_hist2[65535 - (t * 64 + j)];
    part[t] = s; __syncthreads();
    for (int off = 1; off < 1024; off <<= 1) {
        unsigned add = (t >= off) ? part[t - off] : 0u;
        __syncthreads();
        part[t] += add;
        __syncthreads();
    }
    unsigned incl = part[t], excl = incl - s;
    unsigned r = g_r;
    if (excl < r && r <= incl) {
        unsigned cum = excl;
        for (int j = 0; j < 64; j++) {
            int bin = 65535 - (t * 64 + j);
            unsigned h = g_hist2[bin];
            if (r <= cum + h) {
                g_keyT = (g_bhi << 16) | (unsigned)bin;
                g_take = r - cum;
                break;
            }
            cum += h;
        }
    }
}

__global__ void k_finalneg() {
    __shared__ float sce;
    __shared__ unsigned scnt;
    if (threadIdx.x == 0) { sce = 0.f; scnt = 0u; }
    __syncthreads();
    int i = blockIdx.x * blockDim.x + threadIdx.x;
    if (i < ROWS) {
        unsigned key = g_keys[i];
        if (key) {
            if (g_takeAll || key > g_keyT) {
                atomicAdd(&sce, g_ceneg[i]);
                atomicAdd(&scnt, 1u);
            } else if (key == g_keyT) {
                unsigned slot = atomicAdd(&g_eqcnt, 1u);
                if (slot < 4096u) g_eq[slot] = (unsigned)i;
            }
        }
    }
    __syncthreads();
    if (threadIdx.x == 0 && scnt) {
        atomicAdd(&g_cenegsum, sce);
        atomicAdd(&g_negGT, scnt);
    }
}

__global__ void k_eqresolve() {
    if (g_takeAll) return;
    __shared__ float sce;
    if (threadIdx.x == 0) sce = 0.f;
    __syncthreads();
    unsigned E = min(g_eqcnt, 4096u);
    unsigned take = g_take;
    for (unsigned j = threadIdx.x; j < E; j += blockDim.x) {
        unsigned idx = g_eq[j];
        unsigned rank = 0;
        for (unsigned l = 0; l < E; l++) rank += (g_eq[l] < idx) ? 1u : 0u;
        if (rank < take) atomicAdd(&sce, g_ceneg[idx]);
    }
    __syncthreads();
    if (threadIdx.x == 0) atomicAdd(&g_cenegsum, sce);
}

__global__ void k_finalize(float* __restrict__ out) {
    unsigned np = g_numpos;
    unsigned nneg = g_negGT + (g_takeAll ? 0u : g_take);
    unsigned keep = np + nneg;
    out[0] = g_sl1 / (float)max(np, 1u);
    out[1] = (g_cepos + g_cenegsum) / (float)max(keep, 1u);
}

// ---------------- launch ----------------
extern "C" void kernel_launch(void* const* d_in, const int* in_sizes, int n_in,
                              void* d_out, int out_size) {
    const float* loc    = (const float*)d_in[0];
    const float* conf   = (const float*)d_in[1];
    const float* priors = (const float*)d_in[2];
    const float* gtb    = (const float*)d_in[3];
    const int*   gtl    = (const int*)d_in[4];
    float* out = (float*)d_out;

    k_init<<<512, 256>>>();
    k_match<<<dim3((NPRI + 255) / 256, BATCH), 256>>>(priors, gtb);
    k_force<<<1, 32>>>();
    k_bigpass<<<ROWS / 8, 256>>>(loc, conf, priors, gtb, gtl);
    k_select1<<<1, 1024>>>();
    k_hist2<<<(ROWS + 255) / 256, 256>>>();
    k_select2<<<1, 1024>>>();
    k_finalneg<<<(ROWS + 255) / 256, 256>>>();
    k_eqresolve<<<1, 256>>>();
    k_finalize<<<1, 1>>>(out);
}